// round 15
// baseline (speedup 1.0000x reference)
#include <cuda_runtime.h>
#include <cuda_fp16.h>
#include <math.h>
#include <stdint.h>

// ---------------- problem constants ----------------
#define TOK     2048
#define HDIM    1024
#define FDIM    512
#define F2DIM   1024
#define NEXP    64
#define TOPK    8
#define NGRP    8
#define TGRP    4
#define CAPE    1024
#define SKTOT   (TOK*TOPK)
#define SCALE   2.5f
#define KSPLIT  4
#define MAXTILES 192

// ---------------- device scratch ----------------
__device__ __half g_x_h[TOK * HDIM];
__device__ __half g_x_l[TOK * HDIM];
__device__ __half g_gw_h[NEXP * HDIM];
__device__ __half g_gw_l[NEXP * HDIM];
__device__ __half g_sg_h[F2DIM * HDIM];
__device__ __half g_su_h[F2DIM * HDIM];
__device__ __half g_sd_h[HDIM * F2DIM];
__device__ __half g_hb_h[SKTOT * FDIM];
__device__ __half g_hs_h[TOK * F2DIM];
__device__ float g_logits_part[KSPLIT][TOK * NEXP];
__device__ int   g_topk_idx[SKTOT];
__device__ float g_topk_w[SKTOT];
__device__ int   g_counts[NEXP];
__device__ int   g_fill[NEXP];
__device__ int   g_offsets[NEXP];
__device__ int   g_ecount[NEXP];
__device__ int   g_row_token[SKTOT];
__device__ float g_row_weight[SKTOT];
__device__ int   g_tiles[MAXTILES];
__device__ int   g_ntiles;

// ---------------- helpers ----------------
__device__ __forceinline__ float silu_mul_fast(float g, float u) {
    return g / (1.f + __expf(-g)) * u;
}
__device__ __forceinline__ uint32_t smem_u32(const void* p) {
    uint32_t a;
    asm("{ .reg .u64 t; cvta.to.shared.u64 t, %1; cvt.u32.u64 %0, t; }" : "=r"(a) : "l"(p));
    return a;
}
__device__ __forceinline__ uint32_t h_pair(float a, float b) {
    uint32_t r;
    asm("cvt.rn.f16x2.f32 %0, %1, %2;" : "=r"(r) : "f"(b), "f"(a));
    return r;
}

// ---------------- mma.sync / ldmatrix / cp.async primitives ----------------
__device__ __forceinline__ void ldsm4(uint32_t* r, uint32_t a) {
    asm volatile("ldmatrix.sync.aligned.m8n8.x4.shared.b16 {%0,%1,%2,%3}, [%4];"
                 : "=r"(r[0]), "=r"(r[1]), "=r"(r[2]), "=r"(r[3]) : "r"(a));
}
__device__ __forceinline__ void mma_f16(float* d, const uint32_t* a, const uint32_t* b) {
    asm volatile("mma.sync.aligned.m16n8k16.row.col.f32.f16.f16.f32 "
                 "{%0,%1,%2,%3}, {%4,%5,%6,%7}, {%8,%9}, {%0,%1,%2,%3};"
                 : "+f"(d[0]), "+f"(d[1]), "+f"(d[2]), "+f"(d[3])
                 : "r"(a[0]), "r"(a[1]), "r"(a[2]), "r"(a[3]), "r"(b[0]), "r"(b[1]));
}
#define CP16(dst, src) \
    asm volatile("cp.async.cg.shared.global [%0], [%1], 16;" :: "r"(dst), "l"(src))
#define CP_COMMIT() asm volatile("cp.async.commit_group;" ::: "memory")
#define CP_WAIT1()  asm volatile("cp.async.wait_group 1;" ::: "memory")
#define CP_WAIT0()  asm volatile("cp.async.wait_group 0;" ::: "memory")

// ---------------- SMEM tile layout (K=32 chunks, 3 stages) ----------------
#define STRIDE   80
#define PLANE    10240
#define SM_TILES 1024
#define SMEM_GEMM (SM_TILES + 6 * PLANE)   // 62464
#define LSTRIDE  80
#define SMEM_LOG (1024 + 2 * 30720)        // 62464

__device__ __forceinline__ uint32_t toff(int stage, int p) {
    return SM_TILES + (uint32_t)(stage * 2 + p) * PLANE;
}

// 1-product K=32 chunk: acc += A*B  (planes: 0=A 1=B)
__device__ __forceinline__ void mma_tile1(float (&acc)[4][4][4], uint32_t smb, int stage,
                                          int wm, int wn, int lane) {
    const uint32_t base = smb + SM_TILES + (uint32_t)stage * 2 * PLANE;
    const uint32_t la = base + (uint32_t)((wm * 64 + (lane & 15)) * STRIDE) + (uint32_t)((lane >> 4) << 4);
    const uint32_t lb = base + PLANE + ((lane & 16) ? 8 * STRIDE : 0)
                        + (uint32_t)((wn * 32 + (lane & 7)) * STRIDE)
                        + (uint32_t)(((lane >> 3) & 1) << 4);
#pragma unroll
    for (int ks = 0; ks < 2; ks++) {
        const int ko = ks * 32;
        uint32_t ah[4][4], bf[2][4];
#pragma unroll
        for (int mi = 0; mi < 4; mi++) ldsm4(ah[mi], la + mi * 16 * STRIDE + ko);
        ldsm4(bf[0], lb + ko);
        ldsm4(bf[1], lb + 16 * STRIDE + ko);
#pragma unroll
        for (int mi = 0; mi < 4; mi++)
#pragma unroll
            for (int ni = 0; ni < 4; ni++)
                mma_f16(acc[mi][ni], ah[mi], &bf[ni >> 1][(ni & 1) * 2]);
    }
}

// ---------------- loaders ----------------
__device__ __forceinline__ void ldg16f(float* r, const float* __restrict__ p) {
#pragma unroll
    for (int i = 0; i < 4; i++) *(float4*)(r + i * 4) = *(const float4*)(p + i * 4);
}
__device__ __forceinline__ void sts_h16(char* p, const float* v) {
    uint4 H0, H1;
    H0.x = h_pair(v[0], v[1]);   H0.y = h_pair(v[2], v[3]);
    H0.z = h_pair(v[4], v[5]);   H0.w = h_pair(v[6], v[7]);
    H1.x = h_pair(v[8], v[9]);   H1.y = h_pair(v[10], v[11]);
    H1.z = h_pair(v[12], v[13]); H1.w = h_pair(v[14], v[15]);
    *(uint4*)p = H0; *(uint4*)(p + 16) = H1;
}
__device__ __forceinline__ void cp32B(uint32_t d, const __half* s) {
    CP16(d, s); CP16(d + 16, s + 8);
}

// ---------------- presplit kernels (forked across streams) ----------------
#define NX (TOK * HDIM / 8)
#define NG (NEXP * HDIM / 8)
#define NS (F2DIM * HDIM / 8)

// 2-plane: x + gw (gates logits)
__global__ __launch_bounds__(256) void presplitA_kernel(const float* __restrict__ x,
                                                        const float* __restrict__ gw) {
    int i = blockIdx.x * blockDim.x + threadIdx.x;
    if (i >= NX + NG) return;
    const float* s;
    __half *hq, *lq;
    int j = i;
    if (j < NX) { s = x; hq = g_x_h; lq = g_x_l; }
    else { j -= NX; s = gw; hq = g_gw_h; lq = g_gw_l; }

    const float4* p = (const float4*)s + (size_t)j * 2;
    float4 v0 = p[0], v1 = p[1];
    float vv[8] = {v0.x, v0.y, v0.z, v0.w, v1.x, v1.y, v1.z, v1.w};
    uint4 H, L;
    uint32_t* hp = (uint32_t*)&H;
    uint32_t* lp = (uint32_t*)&L;
#pragma unroll
    for (int q = 0; q < 4; q++) {
        __half2 h = __floats2half2_rn(vv[2 * q], vv[2 * q + 1]);
        float2 bk = __half22float2(h);
        __half2 l = __floats2half2_rn(vv[2 * q] - bk.x, vv[2 * q + 1] - bk.y);
        hp[q] = *(uint32_t*)&h;
        lp[q] = *(uint32_t*)&l;
    }
    ((uint4*)hq)[j] = H;
    ((uint4*)lq)[j] = L;
}
// 1-plane: shared-expert weights (gates sg1/sg2 only)
__global__ __launch_bounds__(256) void presplitB_kernel(const float* __restrict__ sg,
                                                        const float* __restrict__ su,
                                                        const float* __restrict__ sd) {
    int i = blockIdx.x * blockDim.x + threadIdx.x;
    const float* s = (blockIdx.y == 0) ? sg : (blockIdx.y == 1) ? su : sd;
    __half* hq     = (blockIdx.y == 0) ? g_sg_h : (blockIdx.y == 1) ? g_su_h : g_sd_h;
    const float4* p = (const float4*)s + (size_t)i * 2;
    float4 v0 = p[0], v1 = p[1];
    uint4 H;
    H.x = h_pair(v0.x, v0.y); H.y = h_pair(v0.z, v0.w);
    H.z = h_pair(v1.x, v1.y); H.w = h_pair(v1.z, v1.w);
    ((uint4*)hq)[i] = H;
}

// =====================================================================
// logits (split-K)
// =====================================================================
__global__ void __launch_bounds__(256, 2) logits_kernel() {
    extern __shared__ char sm[];
    const int tid = threadIdx.x, lane = tid & 31, wid = tid >> 5;
    const int wm = wid & 1, wn = wid >> 1;
    const int m0 = blockIdx.x * 128;
    const int kz = blockIdx.y;
    const int kbase = kz * (HDIM / KSPLIT);
    const uint32_t smb = smem_u32(sm);

    if (blockIdx.x == 0 && kz == 0 && tid < NEXP) { g_counts[tid] = 0; g_fill[tid] = 0; }

    const int lr = tid >> 1, kseg = (tid & 1) * 16;
    const uint32_t soffA = (uint32_t)(lr * LSTRIDE + kseg * 2);
    const __half* axh = g_x_h + (size_t)(m0 + lr) * HDIM + kbase + kseg;
    const __half* axl = g_x_l + (size_t)(m0 + lr) * HDIM + kbase + kseg;
    const int br = tid >> 2, bks = (tid & 3) * 8;
    const uint32_t soffB = (uint32_t)(br * LSTRIDE + bks * 2);
    const __half* bgh = g_gw_h + (size_t)br * HDIM + kbase + bks;
    const __half* bgl = g_gw_l + (size_t)br * HDIM + kbase + bks;

    auto bufb = [&](int buf) { return smb + 1024 + (uint32_t)buf * 30720u; };

    float acc[4][2][4];
#pragma unroll
    for (int i = 0; i < 4; i++)
#pragma unroll
        for (int j = 0; j < 2; j++)
#pragma unroll
            for (int k = 0; k < 4; k++) acc[i][j][k] = 0.f;

    cp32B(bufb(0) + soffA, axh);
    cp32B(bufb(0) + 10240 + soffA, axl);
    CP16(bufb(0) + 20480 + soffB, bgh);
    CP16(bufb(0) + 25600 + soffB, bgl);
    CP_COMMIT();

    int buf = 0;
    const int NCH = HDIM / KSPLIT / 32;
    for (int ch = 0; ch < NCH; ch++) {
        if (ch + 1 < NCH) {
            int k0 = (ch + 1) * 32;
            cp32B(bufb(buf ^ 1) + soffA, axh + k0);
            cp32B(bufb(buf ^ 1) + 10240 + soffA, axl + k0);
            CP16(bufb(buf ^ 1) + 20480 + soffB, bgh + k0);
            CP16(bufb(buf ^ 1) + 25600 + soffB, bgl + k0);
            CP_COMMIT(); CP_WAIT1();
        } else CP_WAIT0();
        __syncthreads();
        {
            const uint32_t base = bufb(buf);
            const uint32_t la = base + (uint32_t)((wm * 64 + (lane & 15)) * LSTRIDE) + (uint32_t)((lane >> 4) << 4);
            const uint32_t lb = base + 20480 + ((lane & 16) ? 8 * LSTRIDE : 0)
                                + (uint32_t)((wn * 16 + (lane & 7)) * LSTRIDE)
                                + (uint32_t)(((lane >> 3) & 1) << 4);
#pragma unroll
            for (int ks = 0; ks < 2; ks++) {
                const int ko = ks * 32;
                uint32_t ah[4][4], al_[4][4], bh[4], bl[4];
#pragma unroll
                for (int mi = 0; mi < 4; mi++) ldsm4(ah[mi], la + mi * 16 * LSTRIDE + ko);
#pragma unroll
                for (int mi = 0; mi < 4; mi++) ldsm4(al_[mi], la + 10240 + mi * 16 * LSTRIDE + ko);
                ldsm4(bh, lb + ko);
                ldsm4(bl, lb + 5120 + ko);
#pragma unroll
                for (int mi = 0; mi < 4; mi++)
#pragma unroll
                    for (int ni = 0; ni < 2; ni++) {
                        mma_f16(acc[mi][ni], ah[mi],  &bh[ni * 2]);
                        mma_f16(acc[mi][ni], al_[mi], &bh[ni * 2]);
                        mma_f16(acc[mi][ni], ah[mi],  &bl[ni * 2]);
                    }
            }
        }
        __syncthreads();
        buf ^= 1;
    }

    float* lp = g_logits_part[kz];
#pragma unroll
    for (int mi = 0; mi < 4; mi++) {
        int r = m0 + wm * 64 + mi * 16 + (lane >> 2);
#pragma unroll
        for (int ni = 0; ni < 2; ni++) {
            int col = wn * 16 + ni * 8 + 2 * (lane & 3);
            float* d = acc[mi][ni];
            *(float2*)(lp + (size_t)r * NEXP + col)       = make_float2(d[0], d[1]);
            *(float2*)(lp + (size_t)(r + 8) * NEXP + col) = make_float2(d[2], d[3]);
        }
    }
}

// =====================================================================
// topk: one warp per token; sums split-K partials
// =====================================================================
__global__ __launch_bounds__(256) void topk_kernel(const float* __restrict__ eb) {
    const int lane = threadIdx.x & 31;
    const int t = blockIdx.x * 8 + (threadIdx.x >> 5);
    const unsigned FULL = 0xffffffffu;

    float l0 = 0.f, l1 = 0.f;
#pragma unroll
    for (int kz = 0; kz < KSPLIT; kz++) {
        l0 += g_logits_part[kz][(size_t)t * NEXP + lane];
        l1 += g_logits_part[kz][(size_t)t * NEXP + 32 + lane];
    }
    float s0 = 1.f / (1.f + expf(-l0));
    float s1 = 1.f / (1.f + expf(-l1));
    float f0 = s0 + eb[lane];
    float f1 = s1 + eb[lane + 32];

    float m1a = f0, m2a = -1e30f, m1b = f1, m2b = -1e30f;
#pragma unroll
    for (int off = 4; off; off >>= 1) {
        float o1 = __shfl_xor_sync(FULL, m1a, off), o2 = __shfl_xor_sync(FULL, m2a, off);
        if (o1 >= m1a) { m2a = fmaxf(m1a, o2); m1a = o1; } else m2a = fmaxf(m2a, o1);
        float p1 = __shfl_xor_sync(FULL, m1b, off), p2 = __shfl_xor_sync(FULL, m2b, off);
        if (p1 >= m1b) { m2b = fmaxf(m1b, p2); m1b = p1; } else m2b = fmaxf(m2b, p1);
    }
    float g2lo = m1a + m2a;
    float g2hi = m1b + m2b;

    float gsc[NGRP];
#pragma unroll
    for (int g = 0; g < 4; g++) gsc[g]     = __shfl_sync(FULL, g2lo, g * 8);
#pragma unroll
    for (int g = 0; g < 4; g++) gsc[4 + g] = __shfl_sync(FULL, g2hi, g * 8);

    unsigned gsel = 0;
#pragma unroll
    for (int it = 0; it < TGRP; it++) {
        float best = -1e30f; int bi = 0;
#pragma unroll
        for (int g = 0; g < NGRP; g++)
            if (!((gsel >> g) & 1) && gsc[g] > best) { best = gsc[g]; bi = g; }
        gsel |= 1u << bi;
    }

    float t0 = ((gsel >> (lane >> 3)) & 1)       ? f0 : 0.f;
    float t1 = ((gsel >> (4 + (lane >> 3))) & 1) ? f1 : 0.f;

    int   myidx = 0;
    float myw = 0.f;
    float wsum = 0.f;
#pragma unroll
    for (int k = 0; k < TOPK; k++) {
        float v; int ix;
        if (t1 > t0) { v = t1; ix = lane + 32; } else { v = t0; ix = lane; }
#pragma unroll
        for (int off = 16; off; off >>= 1) {
            float ov = __shfl_xor_sync(FULL, v, off);
            int   oi = __shfl_xor_sync(FULL, ix, off);
            if (ov > v || (ov == v && oi < ix)) { v = ov; ix = oi; }
        }
        float wv = __shfl_sync(FULL, (ix < 32) ? s0 : s1, ix & 31);
        if (lane == k) { myidx = ix; myw = wv; }
        wsum += wv;
        if (lane == (ix & 31)) { if (ix < 32) t0 = -1e30f; else t1 = -1e30f; }
    }
    float inv = SCALE / (wsum + 1e-20f);
    if (lane < TOPK) {
        g_topk_idx[t * TOPK + lane] = myidx;
        g_topk_w[t * TOPK + lane] = myw * inv;
        atomicAdd(&g_counts[myidx], 1);
    }
}

// =====================================================================
// assign: folds prefix scan; block 0 publishes offsets/ecount + tile table
// =====================================================================
__global__ void assign_kernel() {
    __shared__ int offs[NEXP];
    const int tid = threadIdx.x;
    if (tid == 0) {
        int run = 0, nt = 0;
#pragma unroll
        for (int e = 0; e < NEXP; e++) {
            int c = g_counts[e];
            int cc = c < CAPE ? c : CAPE;
            offs[e] = run;
            if (blockIdx.x == 0) {
                g_offsets[e] = run; g_ecount[e] = cc;
                for (int mt = 0; mt * 128 < cc; mt++) g_tiles[nt++] = (e << 8) | mt;
            }
            run += cc;
        }
        if (blockIdx.x == 0) g_ntiles = nt;
    }
    __syncthreads();
    int s = blockIdx.x * blockDim.x + tid;
    if (s >= SKTOT) return;
    int e = g_topk_idx[s];
    int p = atomicAdd(&g_fill[e], 1);
    if (p < CAPE) {
        int r = offs[e] + p;
        g_row_token[r] = s / TOPK;
        g_row_weight[r] = g_topk_w[s];
    }
}

// =====================================================================
// Expert GEMM1: dense tile list; t -> (tile>>3 = row-tile, t&7 = f-tile)
// =====================================================================
__global__ void __launch_bounds__(256, 2) eg1_kernel(const float* __restrict__ w1,
                                                     const float* __restrict__ w3) {
    extern __shared__ char sm[];
    const int tid = threadIdx.x, lane = tid & 31, wid = tid >> 5;
    const int wm = wid & 1, wn = wid >> 1;
    const int t = blockIdx.x;
    if (t >= g_ntiles * 8) return;
    const int tile = g_tiles[t >> 3];
    const int e  = tile >> 8;
    const int m0 = (tile & 255) * 128;
    const int f0 = (t & 7) * 64;
    const int me = g_ecount[e];
    const int roff = g_offsets[e];
    const uint32_t smb = smem_u32(sm);

    int* toks = (int*)sm;
    if (tid < 128) {
        int m = m0 + tid;
        toks[tid] = g_row_token[roff + ((m < me) ? m : 0)];
    }
    __syncthreads();

    const int lr = tid >> 1, kseg = (tid & 1) * 16;
    const uint32_t soff = (uint32_t)(lr * STRIDE + kseg * 2);
    const __half* axh = g_x_h + (size_t)toks[lr] * HDIM + kseg;
    const float* bp = ((lr & 1) ? w3 : w1) + ((size_t)e * FDIM + f0 + (lr >> 1)) * HDIM + kseg;

    float acc[4][4][4];
#pragma unroll
    for (int i = 0; i < 4; i++)
#pragma unroll
        for (int j = 0; j < 4; j++)
#pragma unroll
            for (int k = 0; k < 4; k++) acc[i][j][k] = 0.f;

    const int NCH = HDIM / 32;
    float rb[16], rbn[16];
    ldg16f(rb, bp);
    sts_h16(sm + toff(0, 1) + soff, rb);
    ldg16f(rb, bp + 32);
    sts_h16(sm + toff(1, 1) + soff, rb);
    ldg16f(rbn, bp + 64);
    cp32B(smb + toff(0, 0) + soff, axh);
    CP_COMMIT();
    cp32B(smb + toff(1, 0) + soff, axh + 32);
    CP_COMMIT();

    for (int ch = 0; ch < NCH; ch++) {
        if (ch + 1 < NCH) CP_WAIT1(); else CP_WAIT0();
        __syncthreads();
        if (ch + 2 < NCH) {
            int st = (ch + 2) % 3;
            sts_h16(sm + toff(st, 1) + soff, rbn);
            cp32B(smb + toff(st, 0) + soff, axh + (ch + 2) * 32);
            CP_COMMIT();
            if (ch + 3 < NCH) ldg16f(rbn, bp + (ch + 3) * 32);
        }
        mma_tile1(acc, smb, ch % 3, wm, wn, lane);
    }

#pragma unroll
    for (int mi = 0; mi < 4; mi++) {
        int r = m0 + wm * 64 + mi * 16 + (lane >> 2);
#pragma unroll
        for (int ni = 0; ni < 4; ni++) {
            int lc = f0 + wn * 16 + ni * 4 + (lane & 3);
            float* d = acc[mi][ni];
            if (r < me)
                g_hb_h[(size_t)(roff + r) * FDIM + lc] = __float2half_rn(silu_mul_fast(d[0], d[1]));
            if (r + 8 < me)
                g_hb_h[(size_t)(roff + r + 8) * FDIM + lc] = __float2half_rn(silu_mul_fast(d[2], d[3]));
        }
    }
}

// =====================================================================
// Expert GEMM2: dense tile list; t -> (row-tile, n-tile)
// =====================================================================
__global__ void __launch_bounds__(256, 2) eg2_kernel(const float* __restrict__ w2,
                                                     float* __restrict__ out) {
    extern __shared__ char sm[];
    const int tid = threadIdx.x, lane = tid & 31, wid = tid >> 5;
    const int wm = wid & 1, wn = wid >> 1;
    const int t = blockIdx.x;
    if (t >= g_ntiles * 8) return;
    const int tile = g_tiles[t >> 3];
    const int e  = tile >> 8;
    const int m0 = (tile & 255) * 128;
    const int n0 = (t & 7) * 128;
    const int me = g_ecount[e];
    const int roff = g_offsets[e];
    const uint32_t smb = smem_u32(sm);

    int*   toks = (int*)sm;
    float* wro  = (float*)(sm + 512);
    if (tid < 128) {
        int m = m0 + tid;
        bool v = m < me;
        toks[tid] = v ? g_row_token[roff + m] : 0;
        wro[tid]  = v ? g_row_weight[roff + m] : 0.f;
    }
    __syncthreads();

    const int lr = tid >> 1, kseg = (tid & 1) * 16;
    const uint32_t soff = (uint32_t)(lr * STRIDE + kseg * 2);
    int mm = m0 + lr;
    size_t arow = (size_t)(roff + ((mm < me) ? mm : (me - 1)));
    const __half* axh = g_hb_h + arow * FDIM + kseg;
    const float* bp = w2 + ((size_t)e * HDIM + n0 + lr) * FDIM + kseg;

    float acc[4][4][4];
#pragma unroll
    for (int i = 0; i < 4; i++)
#pragma unroll
        for (int j = 0; j < 4; j++)
#pragma unroll
            for (int k = 0; k < 4; k++) acc[i][j][k] = 0.f;

    const int NCH = FDIM / 32;
    float rb[16], rbn[16];
    ldg16f(rb, bp);
    sts_h16(sm + toff(0, 1) + soff, rb);
    ldg16f(rb, bp + 32);
    sts_h16(sm + toff(1, 1) + soff, rb);
    ldg16f(rbn, bp + 64);
    cp32B(smb + toff(0, 0) + soff, axh);
    CP_COMMIT();
    cp32B(smb + toff(1, 0) + soff, axh + 32);
    CP_COMMIT();

    for (int ch = 0; ch < NCH; ch++) {
        if (ch + 1 < NCH) CP_WAIT1(); else CP_WAIT0();
        __syncthreads();
        if (ch + 2 < NCH) {
            int st = (ch + 2) % 3;
            sts_h16(sm + toff(st, 1) + soff, rbn);
            cp32B(smb + toff(st, 0) + soff, axh + (ch + 2) * 32);
            CP_COMMIT();
            if (ch + 3 < NCH) ldg16f(rbn, bp + (ch + 3) * 32);
        }
        mma_tile1(acc, smb, ch % 3, wm, wn, lane);
    }

#pragma unroll
    for (int mi = 0; mi < 4; mi++) {
        int lrow = wm * 64 + mi * 16 + (lane >> 2);
        int r = m0 + lrow;
        int t0 = toks[lrow], t1 = toks[lrow + 8];
        float w0 = wro[lrow], w1v = wro[lrow + 8];
#pragma unroll
        for (int ni = 0; ni < 4; ni++) {
            int col = n0 + wn * 32 + ni * 8 + 2 * (lane & 3);
            float* d = acc[mi][ni];
            if (r < me) {
                atomicAdd(out + (size_t)t0 * HDIM + col,     d[0] * w0);
                atomicAdd(out + (size_t)t0 * HDIM + col + 1, d[1] * w0);
            }
            if (r + 8 < me) {
                atomicAdd(out + (size_t)t1 * HDIM + col,     d[2] * w1v);
                atomicAdd(out + (size_t)t1 * HDIM + col + 1, d[3] * w1v);
            }
        }
    }
}

// =====================================================================
// Shared GEMM1 (3-stage ring)
// =====================================================================
__global__ void __launch_bounds__(256, 2) sg1_kernel() {
    extern __shared__ char sm[];
    const int tid = threadIdx.x, lane = tid & 31, wid = tid >> 5;
    const int wm = wid & 1, wn = wid >> 1;
    const int m0 = blockIdx.y * 128;
    const int f0 = blockIdx.x * 64;
    const uint32_t smb = smem_u32(sm);

    const int lr = tid >> 1, kseg = (tid & 1) * 16;
    const uint32_t soff = (uint32_t)(lr * STRIDE + kseg * 2);
    const __half* axh = g_x_h + (size_t)(m0 + lr) * HDIM + kseg;
    const __half* bxh = ((lr & 1) ? g_su_h : g_sg_h) + (size_t)(f0 + (lr >> 1)) * HDIM + kseg;

    float acc[4][4][4];
#pragma unroll
    for (int i = 0; i < 4; i++)
#pragma unroll
        for (int j = 0; j < 4; j++)
#pragma unroll
            for (int k = 0; k < 4; k++) acc[i][j][k] = 0.f;

    const int NCH = HDIM / 32;
    cp32B(smb + toff(0, 0) + soff, axh);
    cp32B(smb + toff(0, 1) + soff, bxh);
    CP_COMMIT();
    cp32B(smb + toff(1, 0) + soff, axh + 32);
    cp32B(smb + toff(1, 1) + soff, bxh + 32);
    CP_COMMIT();

    for (int ch = 0; ch < NCH; ch++) {
        if (ch + 1 < NCH) CP_WAIT1(); else CP_WAIT0();
        __syncthreads();
        if (ch + 2 < NCH) {
            int st = (ch + 2) % 3;
            int k0 = (ch + 2) * 32;
            cp32B(smb + toff(st, 0) + soff, axh + k0);
            cp32B(smb + toff(st, 1) + soff, bxh + k0);
            CP_COMMIT();
        }
        mma_tile1(acc, smb, ch % 3, wm, wn, lane);
    }

#pragma unroll
    for (int mi = 0; mi < 4; mi++) {
        int r = m0 + wm * 64 + mi * 16 + (lane >> 2);
#pragma unroll
        for (int ni = 0; ni < 4; ni++) {
            int lc = f0 + wn * 16 + ni * 4 + (lane & 3);
            float* d = acc[mi][ni];
            g_hs_h[(size_t)r * F2DIM + lc]       = __float2half_rn(silu_mul_fast(d[0], d[1]));
            g_hs_h[(size_t)(r + 8) * F2DIM + lc] = __float2half_rn(silu_mul_fast(d[2], d[3]));
        }
    }
}

// =====================================================================
// Shared GEMM2 (3-stage ring)
// =====================================================================
__global__ void __launch_bounds__(256, 2) sg2_kernel(float* __restrict__ out) {
    extern __shared__ char sm[];
    const int tid = threadIdx.x, lane = tid & 31, wid = tid >> 5;
    const int wm = wid & 1, wn = wid >> 1;
    const int m0 = blockIdx.y * 128;
    const int n0 = blockIdx.x * 128;
    const uint32_t smb = smem_u32(sm);

    const int lr = tid >> 1, kseg = (tid & 1) * 16;
    const uint32_t soff = (uint32_t)(lr * STRIDE + kseg * 2);
    const __half* axh = g_hs_h + (size_t)(m0 + lr) * F2DIM + kseg;
    const __half* bxh = g_sd_h + (size_t)(n0 + lr) * F2DIM + kseg;

    float acc[4][4][4];
#pragma unroll
    for (int i = 0; i < 4; i++)
#pragma unroll
        for (int j = 0; j < 4; j++)
#pragma unroll
            for (int k = 0; k < 4; k++) acc[i][j][k] = 0.f;

    const int NCH = F2DIM / 32;
    cp32B(smb + toff(0, 0) + soff, axh);
    cp32B(smb + toff(0, 1) + soff, bxh);
    CP_COMMIT();
    cp32B(smb + toff(1, 0) + soff, axh + 32);
    cp32B(smb + toff(1, 1) + soff, bxh + 32);
    CP_COMMIT();

    for (int ch = 0; ch < NCH; ch++) {
        if (ch + 1 < NCH) CP_WAIT1(); else CP_WAIT0();
        __syncthreads();
        if (ch + 2 < NCH) {
            int st = (ch + 2) % 3;
            int k0 = (ch + 2) * 32;
            cp32B(smb + toff(st, 0) + soff, axh + k0);
            cp32B(smb + toff(st, 1) + soff, bxh + k0);
            CP_COMMIT();
        }
        mma_tile1(acc, smb, ch % 3, wm, wn, lane);
    }

#pragma unroll
    for (int mi = 0; mi < 4; mi++) {
        int r = m0 + wm * 64 + mi * 16 + (lane >> 2);
#pragma unroll
        for (int ni = 0; ni < 4; ni++) {
            int col = n0 + wn * 32 + ni * 8 + 2 * (lane & 3);
            float* d = acc[mi][ni];
            *(float2*)(out + (size_t)r * HDIM + col)       = make_float2(d[0], d[1]);
            *(float2*)(out + (size_t)(r + 8) * HDIM + col) = make_float2(d[2], d[3]);
        }
    }
}

// ---------------- launch ----------------
extern "C" void kernel_launch(void* const* d_in, const int* in_sizes, int n_in,
                              void* d_out, int out_size) {
    const float* x   = (const float*)d_in[0];
    const float* gw  = (const float*)d_in[1];
    const float* eb  = (const float*)d_in[2];
    const float* w1  = (const float*)d_in[3];
    const float* w2  = (const float*)d_in[4];
    const float* w3  = (const float*)d_in[5];
    const float* sg  = (const float*)d_in[6];
    const float* su  = (const float*)d_in[7];
    const float* sd  = (const float*)d_in[8];
    float* out = (float*)d_out;

    static bool init_done = false;
    static cudaStream_t s2;
    static cudaEvent_t evB;
    if (!init_done) {
        cudaFuncSetAttribute(logits_kernel, cudaFuncAttributeMaxDynamicSharedMemorySize, SMEM_LOG);
        cudaFuncSetAttribute(eg1_kernel, cudaFuncAttributeMaxDynamicSharedMemorySize, SMEM_GEMM);
        cudaFuncSetAttribute(sg1_kernel, cudaFuncAttributeMaxDynamicSharedMemorySize, SMEM_GEMM);
        cudaFuncSetAttribute(eg2_kernel, cudaFuncAttributeMaxDynamicSharedMemorySize, SMEM_GEMM);
        cudaFuncSetAttribute(sg2_kernel, cudaFuncAttributeMaxDynamicSharedMemorySize, SMEM_GEMM);
        cudaStreamCreateWithFlags(&s2, cudaStreamNonBlocking);
        cudaEventCreateWithFlags(&evB, cudaEventDisableTiming);
        init_done = true;
    }

    // branch B on s2: shared-weight presplit -> sg1 -> sg2 (writes out)
    presplitB_kernel<<<dim3(NS / 256, 3), 256, 0, s2>>>(sg, su, sd);
    // x presplit on s2 too? NO: sg1 needs g_x_h. Put x+gw on main, sg1 must wait for it.
    presplitA_kernel<<<(NX + NG + 255) / 256, 256>>>(x, gw);
    cudaEvent_t evA;
    static cudaEvent_t evA_s;
    static bool ev_init = false;
    if (!ev_init) { cudaEventCreateWithFlags(&evA_s, cudaEventDisableTiming); ev_init = true; }
    evA = evA_s;
    cudaEventRecord(evA, 0);
    cudaStreamWaitEvent(s2, evA, 0);   // sg1 needs g_x_h from presplitA
    sg1_kernel<<<dim3(F2DIM / 64, TOK / 128), 256, SMEM_GEMM, s2>>>();
    sg2_kernel<<<dim3(HDIM / 128, TOK / 128), 256, SMEM_GEMM, s2>>>(out);
    cudaEventRecord(evB, s2);

    // branch A on main: routing + expert up-proj
    logits_kernel<<<dim3(TOK / 128, KSPLIT), 256, SMEM_LOG>>>();
    topk_kernel<<<TOK / 8, 256>>>(eb);
    assign_kernel<<<SKTOT / 256, 256>>>();
    eg1_kernel<<<MAXTILES * 8, 256, SMEM_GEMM>>>(w1, w3);

    // join: eg2 needs eg1 (main) AND sg2's out (s2)
    cudaStreamWaitEvent(0, evB, 0);
    eg2_kernel<<<MAXTILES * 8, 256, SMEM_GEMM>>>(w2, out);
}

// round 16
// speedup vs baseline: 1.0473x; 1.0473x over previous
#include <cuda_runtime.h>
#include <cuda_fp16.h>
#include <math.h>
#include <stdint.h>

// ---------------- problem constants ----------------
#define TOK     2048
#define HDIM    1024
#define FDIM    512
#define F2DIM   1024
#define NEXP    64
#define TOPK    8
#define NGRP    8
#define TGRP    4
#define CAPE    1024
#define SKTOT   (TOK*TOPK)
#define SCALE   2.5f
#define KSPLIT  4
#define MAXTILES 192
#define HTILES  (MAXTILES / 2 + 1)

// ---------------- device scratch ----------------
__device__ __half g_x_h[TOK * HDIM];
__device__ __half g_x_l[TOK * HDIM];
__device__ __half g_gw_h[NEXP * HDIM];
__device__ __half g_gw_l[NEXP * HDIM];
__device__ __half g_sg_h[F2DIM * HDIM];
__device__ __half g_su_h[F2DIM * HDIM];
__device__ __half g_sd_h[HDIM * F2DIM];
__device__ __half g_hb_h[SKTOT * FDIM];
__device__ __half g_hs_h[TOK * F2DIM];
__device__ float g_logits_part[KSPLIT][TOK * NEXP];
__device__ int   g_topk_idx[SKTOT];
__device__ float g_topk_w[SKTOT];
__device__ int   g_counts[NEXP];
__device__ int   g_fill[NEXP];
__device__ int   g_offsets[NEXP];
__device__ int   g_ecount[NEXP];
__device__ int   g_row_token[SKTOT];
__device__ float g_row_weight[SKTOT];
__device__ int   g_tiles2[2][HTILES];
__device__ int   g_nt2[2];

// ---------------- helpers ----------------
__device__ __forceinline__ float silu_mul_fast(float g, float u) {
    return g / (1.f + __expf(-g)) * u;
}
__device__ __forceinline__ uint32_t smem_u32(const void* p) {
    uint32_t a;
    asm("{ .reg .u64 t; cvta.to.shared.u64 t, %1; cvt.u32.u64 %0, t; }" : "=r"(a) : "l"(p));
    return a;
}
__device__ __forceinline__ uint32_t h_pair(float a, float b) {
    uint32_t r;
    asm("cvt.rn.f16x2.f32 %0, %1, %2;" : "=r"(r) : "f"(b), "f"(a));
    return r;
}

// ---------------- mma.sync / ldmatrix / cp.async primitives ----------------
__device__ __forceinline__ void ldsm4(uint32_t* r, uint32_t a) {
    asm volatile("ldmatrix.sync.aligned.m8n8.x4.shared.b16 {%0,%1,%2,%3}, [%4];"
                 : "=r"(r[0]), "=r"(r[1]), "=r"(r[2]), "=r"(r[3]) : "r"(a));
}
__device__ __forceinline__ void mma_f16(float* d, const uint32_t* a, const uint32_t* b) {
    asm volatile("mma.sync.aligned.m16n8k16.row.col.f32.f16.f16.f32 "
                 "{%0,%1,%2,%3}, {%4,%5,%6,%7}, {%8,%9}, {%0,%1,%2,%3};"
                 : "+f"(d[0]), "+f"(d[1]), "+f"(d[2]), "+f"(d[3])
                 : "r"(a[0]), "r"(a[1]), "r"(a[2]), "r"(a[3]), "r"(b[0]), "r"(b[1]));
}
#define CP16(dst, src) \
    asm volatile("cp.async.cg.shared.global [%0], [%1], 16;" :: "r"(dst), "l"(src))
#define CP_COMMIT() asm volatile("cp.async.commit_group;" ::: "memory")
#define CP_WAIT1()  asm volatile("cp.async.wait_group 1;" ::: "memory")
#define CP_WAIT0()  asm volatile("cp.async.wait_group 0;" ::: "memory")

// ---------------- SMEM tile layout (K=32 chunks, 3 stages) ----------------
#define STRIDE   80
#define PLANE    10240
#define SM_TILES 1024
#define SMEM_GEMM (SM_TILES + 6 * PLANE)   // 62464
#define LSTRIDE  80
#define SMEM_LOG (1024 + 2 * 30720)        // 62464

__device__ __forceinline__ uint32_t toff(int stage, int p) {
    return SM_TILES + (uint32_t)(stage * 2 + p) * PLANE;
}

// 1-product K=32 chunk: acc += A*B  (planes: 0=A 1=B)
__device__ __forceinline__ void mma_tile1(float (&acc)[4][4][4], uint32_t smb, int stage,
                                          int wm, int wn, int lane) {
    const uint32_t base = smb + SM_TILES + (uint32_t)stage * 2 * PLANE;
    const uint32_t la = base + (uint32_t)((wm * 64 + (lane & 15)) * STRIDE) + (uint32_t)((lane >> 4) << 4);
    const uint32_t lb = base + PLANE + ((lane & 16) ? 8 * STRIDE : 0)
                        + (uint32_t)((wn * 32 + (lane & 7)) * STRIDE)
                        + (uint32_t)(((lane >> 3) & 1) << 4);
#pragma unroll
    for (int ks = 0; ks < 2; ks++) {
        const int ko = ks * 32;
        uint32_t ah[4][4], bf[2][4];
#pragma unroll
        for (int mi = 0; mi < 4; mi++) ldsm4(ah[mi], la + mi * 16 * STRIDE + ko);
        ldsm4(bf[0], lb + ko);
        ldsm4(bf[1], lb + 16 * STRIDE + ko);
#pragma unroll
        for (int mi = 0; mi < 4; mi++)
#pragma unroll
            for (int ni = 0; ni < 4; ni++)
                mma_f16(acc[mi][ni], ah[mi], &bf[ni >> 1][(ni & 1) * 2]);
    }
}

// ---------------- loaders ----------------
__device__ __forceinline__ void ldg16f(float* r, const float* __restrict__ p) {
#pragma unroll
    for (int i = 0; i < 4; i++) *(float4*)(r + i * 4) = *(const float4*)(p + i * 4);
}
__device__ __forceinline__ void sts_h16(char* p, const float* v) {
    uint4 H0, H1;
    H0.x = h_pair(v[0], v[1]);   H0.y = h_pair(v[2], v[3]);
    H0.z = h_pair(v[4], v[5]);   H0.w = h_pair(v[6], v[7]);
    H1.x = h_pair(v[8], v[9]);   H1.y = h_pair(v[10], v[11]);
    H1.z = h_pair(v[12], v[13]); H1.w = h_pair(v[14], v[15]);
    *(uint4*)p = H0; *(uint4*)(p + 16) = H1;
}
__device__ __forceinline__ void cp32B(uint32_t d, const __half* s) {
    CP16(d, s); CP16(d + 16, s + 8);
}

// ---------------- presplit kernels ----------------
#define NX (TOK * HDIM / 8)
#define NG (NEXP * HDIM / 8)
#define NS (F2DIM * HDIM / 8)

__global__ __launch_bounds__(256) void presplitA_kernel(const float* __restrict__ x,
                                                        const float* __restrict__ gw) {
    int i = blockIdx.x * blockDim.x + threadIdx.x;
    if (i >= NX + NG) return;
    const float* s;
    __half *hq, *lq;
    int j = i;
    if (j < NX) { s = x; hq = g_x_h; lq = g_x_l; }
    else { j -= NX; s = gw; hq = g_gw_h; lq = g_gw_l; }

    const float4* p = (const float4*)s + (size_t)j * 2;
    float4 v0 = p[0], v1 = p[1];
    float vv[8] = {v0.x, v0.y, v0.z, v0.w, v1.x, v1.y, v1.z, v1.w};
    uint4 H, L;
    uint32_t* hp = (uint32_t*)&H;
    uint32_t* lp = (uint32_t*)&L;
#pragma unroll
    for (int q = 0; q < 4; q++) {
        __half2 h = __floats2half2_rn(vv[2 * q], vv[2 * q + 1]);
        float2 bk = __half22float2(h);
        __half2 l = __floats2half2_rn(vv[2 * q] - bk.x, vv[2 * q + 1] - bk.y);
        hp[q] = *(uint32_t*)&h;
        lp[q] = *(uint32_t*)&l;
    }
    ((uint4*)hq)[j] = H;
    ((uint4*)lq)[j] = L;
}
__global__ __launch_bounds__(256) void presplitB_kernel(const float* __restrict__ sg,
                                                        const float* __restrict__ su,
                                                        const float* __restrict__ sd) {
    int i = blockIdx.x * blockDim.x + threadIdx.x;
    const float* s = (blockIdx.y == 0) ? sg : (blockIdx.y == 1) ? su : sd;
    __half* hq     = (blockIdx.y == 0) ? g_sg_h : (blockIdx.y == 1) ? g_su_h : g_sd_h;
    const float4* p = (const float4*)s + (size_t)i * 2;
    float4 v0 = p[0], v1 = p[1];
    uint4 H;
    H.x = h_pair(v0.x, v0.y); H.y = h_pair(v0.z, v0.w);
    H.z = h_pair(v1.x, v1.y); H.w = h_pair(v1.z, v1.w);
    ((uint4*)hq)[i] = H;
}

// =====================================================================
// logits (split-K)
// =====================================================================
__global__ void __launch_bounds__(256, 2) logits_kernel() {
    extern __shared__ char sm[];
    const int tid = threadIdx.x, lane = tid & 31, wid = tid >> 5;
    const int wm = wid & 1, wn = wid >> 1;
    const int m0 = blockIdx.x * 128;
    const int kz = blockIdx.y;
    const int kbase = kz * (HDIM / KSPLIT);
    const uint32_t smb = smem_u32(sm);

    if (blockIdx.x == 0 && kz == 0 && tid < NEXP) { g_counts[tid] = 0; g_fill[tid] = 0; }

    const int lr = tid >> 1, kseg = (tid & 1) * 16;
    const uint32_t soffA = (uint32_t)(lr * LSTRIDE + kseg * 2);
    const __half* axh = g_x_h + (size_t)(m0 + lr) * HDIM + kbase + kseg;
    const __half* axl = g_x_l + (size_t)(m0 + lr) * HDIM + kbase + kseg;
    const int br = tid >> 2, bks = (tid & 3) * 8;
    const uint32_t soffB = (uint32_t)(br * LSTRIDE + bks * 2);
    const __half* bgh = g_gw_h + (size_t)br * HDIM + kbase + bks;
    const __half* bgl = g_gw_l + (size_t)br * HDIM + kbase + bks;

    auto bufb = [&](int buf) { return smb + 1024 + (uint32_t)buf * 30720u; };

    float acc[4][2][4];
#pragma unroll
    for (int i = 0; i < 4; i++)
#pragma unroll
        for (int j = 0; j < 2; j++)
#pragma unroll
            for (int k = 0; k < 4; k++) acc[i][j][k] = 0.f;

    cp32B(bufb(0) + soffA, axh);
    cp32B(bufb(0) + 10240 + soffA, axl);
    CP16(bufb(0) + 20480 + soffB, bgh);
    CP16(bufb(0) + 25600 + soffB, bgl);
    CP_COMMIT();

    int buf = 0;
    const int NCH = HDIM / KSPLIT / 32;
    for (int ch = 0; ch < NCH; ch++) {
        if (ch + 1 < NCH) {
            int k0 = (ch + 1) * 32;
            cp32B(bufb(buf ^ 1) + soffA, axh + k0);
            cp32B(bufb(buf ^ 1) + 10240 + soffA, axl + k0);
            CP16(bufb(buf ^ 1) + 20480 + soffB, bgh + k0);
            CP16(bufb(buf ^ 1) + 25600 + soffB, bgl + k0);
            CP_COMMIT(); CP_WAIT1();
        } else CP_WAIT0();
        __syncthreads();
        {
            const uint32_t base = bufb(buf);
            const uint32_t la = base + (uint32_t)((wm * 64 + (lane & 15)) * LSTRIDE) + (uint32_t)((lane >> 4) << 4);
            const uint32_t lb = base + 20480 + ((lane & 16) ? 8 * LSTRIDE : 0)
                                + (uint32_t)((wn * 16 + (lane & 7)) * LSTRIDE)
                                + (uint32_t)(((lane >> 3) & 1) << 4);
#pragma unroll
            for (int ks = 0; ks < 2; ks++) {
                const int ko = ks * 32;
                uint32_t ah[4][4], al_[4][4], bh[4], bl[4];
#pragma unroll
                for (int mi = 0; mi < 4; mi++) ldsm4(ah[mi], la + mi * 16 * LSTRIDE + ko);
#pragma unroll
                for (int mi = 0; mi < 4; mi++) ldsm4(al_[mi], la + 10240 + mi * 16 * LSTRIDE + ko);
                ldsm4(bh, lb + ko);
                ldsm4(bl, lb + 5120 + ko);
#pragma unroll
                for (int mi = 0; mi < 4; mi++)
#pragma unroll
                    for (int ni = 0; ni < 2; ni++) {
                        mma_f16(acc[mi][ni], ah[mi],  &bh[ni * 2]);
                        mma_f16(acc[mi][ni], al_[mi], &bh[ni * 2]);
                        mma_f16(acc[mi][ni], ah[mi],  &bl[ni * 2]);
                    }
            }
        }
        __syncthreads();
        buf ^= 1;
    }

    float* lp = g_logits_part[kz];
#pragma unroll
    for (int mi = 0; mi < 4; mi++) {
        int r = m0 + wm * 64 + mi * 16 + (lane >> 2);
#pragma unroll
        for (int ni = 0; ni < 2; ni++) {
            int col = wn * 16 + ni * 8 + 2 * (lane & 3);
            float* d = acc[mi][ni];
            *(float2*)(lp + (size_t)r * NEXP + col)       = make_float2(d[0], d[1]);
            *(float2*)(lp + (size_t)(r + 8) * NEXP + col) = make_float2(d[2], d[3]);
        }
    }
}

// =====================================================================
// topk
// =====================================================================
__global__ __launch_bounds__(256) void topk_kernel(const float* __restrict__ eb) {
    const int lane = threadIdx.x & 31;
    const int t = blockIdx.x * 8 + (threadIdx.x >> 5);
    const unsigned FULL = 0xffffffffu;

    float l0 = 0.f, l1 = 0.f;
#pragma unroll
    for (int kz = 0; kz < KSPLIT; kz++) {
        l0 += g_logits_part[kz][(size_t)t * NEXP + lane];
        l1 += g_logits_part[kz][(size_t)t * NEXP + 32 + lane];
    }
    float s0 = 1.f / (1.f + expf(-l0));
    float s1 = 1.f / (1.f + expf(-l1));
    float f0 = s0 + eb[lane];
    float f1 = s1 + eb[lane + 32];

    float m1a = f0, m2a = -1e30f, m1b = f1, m2b = -1e30f;
#pragma unroll
    for (int off = 4; off; off >>= 1) {
        float o1 = __shfl_xor_sync(FULL, m1a, off), o2 = __shfl_xor_sync(FULL, m2a, off);
        if (o1 >= m1a) { m2a = fmaxf(m1a, o2); m1a = o1; } else m2a = fmaxf(m2a, o1);
        float p1 = __shfl_xor_sync(FULL, m1b, off), p2 = __shfl_xor_sync(FULL, m2b, off);
        if (p1 >= m1b) { m2b = fmaxf(m1b, p2); m1b = p1; } else m2b = fmaxf(m2b, p1);
    }
    float g2lo = m1a + m2a;
    float g2hi = m1b + m2b;

    float gsc[NGRP];
#pragma unroll
    for (int g = 0; g < 4; g++) gsc[g]     = __shfl_sync(FULL, g2lo, g * 8);
#pragma unroll
    for (int g = 0; g < 4; g++) gsc[4 + g] = __shfl_sync(FULL, g2hi, g * 8);

    unsigned gsel = 0;
#pragma unroll
    for (int it = 0; it < TGRP; it++) {
        float best = -1e30f; int bi = 0;
#pragma unroll
        for (int g = 0; g < NGRP; g++)
            if (!((gsel >> g) & 1) && gsc[g] > best) { best = gsc[g]; bi = g; }
        gsel |= 1u << bi;
    }

    float t0 = ((gsel >> (lane >> 3)) & 1)       ? f0 : 0.f;
    float t1 = ((gsel >> (4 + (lane >> 3))) & 1) ? f1 : 0.f;

    int   myidx = 0;
    float myw = 0.f;
    float wsum = 0.f;
#pragma unroll
    for (int k = 0; k < TOPK; k++) {
        float v; int ix;
        if (t1 > t0) { v = t1; ix = lane + 32; } else { v = t0; ix = lane; }
#pragma unroll
        for (int off = 16; off; off >>= 1) {
            float ov = __shfl_xor_sync(FULL, v, off);
            int   oi = __shfl_xor_sync(FULL, ix, off);
            if (ov > v || (ov == v && oi < ix)) { v = ov; ix = oi; }
        }
        float wv = __shfl_sync(FULL, (ix < 32) ? s0 : s1, ix & 31);
        if (lane == k) { myidx = ix; myw = wv; }
        wsum += wv;
        if (lane == (ix & 31)) { if (ix < 32) t0 = -1e30f; else t1 = -1e30f; }
    }
    float inv = SCALE / (wsum + 1e-20f);
    if (lane < TOPK) {
        g_topk_idx[t * TOPK + lane] = myidx;
        g_topk_w[t * TOPK + lane] = myw * inv;
        atomicAdd(&g_counts[myidx], 1);
    }
}

// =====================================================================
// assign: folds prefix scan; block 0 publishes offsets/ecount + 2 tile tables
// =====================================================================
__global__ void assign_kernel() {
    __shared__ int offs[NEXP];
    const int tid = threadIdx.x;
    if (tid == 0) {
        int run = 0, nt = 0, n0 = 0, n1 = 0;
#pragma unroll
        for (int e = 0; e < NEXP; e++) {
            int c = g_counts[e];
            int cc = c < CAPE ? c : CAPE;
            offs[e] = run;
            if (blockIdx.x == 0) {
                g_offsets[e] = run; g_ecount[e] = cc;
                for (int mt = 0; mt * 128 < cc; mt++) {
                    int v = (e << 8) | mt;
                    if (nt & 1) g_tiles2[1][n1++] = v;
                    else        g_tiles2[0][n0++] = v;
                    nt++;
                }
            }
            run += cc;
        }
        if (blockIdx.x == 0) { g_nt2[0] = n0; g_nt2[1] = n1; }
    }
    __syncthreads();
    int s = blockIdx.x * blockDim.x + tid;
    if (s >= SKTOT) return;
    int e = g_topk_idx[s];
    int p = atomicAdd(&g_fill[e], 1);
    if (p < CAPE) {
        int r = offs[e] + p;
        g_row_token[r] = s / TOPK;
        g_row_weight[r] = g_topk_w[s];
    }
}

// =====================================================================
// Expert GEMM1 (half = tile table index)
// =====================================================================
__global__ void __launch_bounds__(256, 2) eg1_kernel(const float* __restrict__ w1,
                                                     const float* __restrict__ w3,
                                                     int half) {
    extern __shared__ char sm[];
    const int tid = threadIdx.x, lane = tid & 31, wid = tid >> 5;
    const int wm = wid & 1, wn = wid >> 1;
    const int t = blockIdx.x;
    if (t >= g_nt2[half] * 8) return;
    const int tile = g_tiles2[half][t >> 3];
    const int e  = tile >> 8;
    const int m0 = (tile & 255) * 128;
    const int f0 = (t & 7) * 64;
    const int me = g_ecount[e];
    const int roff = g_offsets[e];
    const uint32_t smb = smem_u32(sm);

    int* toks = (int*)sm;
    if (tid < 128) {
        int m = m0 + tid;
        toks[tid] = g_row_token[roff + ((m < me) ? m : 0)];
    }
    __syncthreads();

    const int lr = tid >> 1, kseg = (tid & 1) * 16;
    const uint32_t soff = (uint32_t)(lr * STRIDE + kseg * 2);
    const __half* axh = g_x_h + (size_t)toks[lr] * HDIM + kseg;
    const float* bp = ((lr & 1) ? w3 : w1) + ((size_t)e * FDIM + f0 + (lr >> 1)) * HDIM + kseg;

    float acc[4][4][4];
#pragma unroll
    for (int i = 0; i < 4; i++)
#pragma unroll
        for (int j = 0; j < 4; j++)
#pragma unroll
            for (int k = 0; k < 4; k++) acc[i][j][k] = 0.f;

    const int NCH = HDIM / 32;
    float rb[16], rbn[16];
    ldg16f(rb, bp);
    sts_h16(sm + toff(0, 1) + soff, rb);
    ldg16f(rb, bp + 32);
    sts_h16(sm + toff(1, 1) + soff, rb);
    ldg16f(rbn, bp + 64);
    cp32B(smb + toff(0, 0) + soff, axh);
    CP_COMMIT();
    cp32B(smb + toff(1, 0) + soff, axh + 32);
    CP_COMMIT();

    for (int ch = 0; ch < NCH; ch++) {
        if (ch + 1 < NCH) CP_WAIT1(); else CP_WAIT0();
        __syncthreads();
        if (ch + 2 < NCH) {
            int st = (ch + 2) % 3;
            sts_h16(sm + toff(st, 1) + soff, rbn);
            cp32B(smb + toff(st, 0) + soff, axh + (ch + 2) * 32);
            CP_COMMIT();
            if (ch + 3 < NCH) ldg16f(rbn, bp + (ch + 3) * 32);
        }
        mma_tile1(acc, smb, ch % 3, wm, wn, lane);
    }

#pragma unroll
    for (int mi = 0; mi < 4; mi++) {
        int r = m0 + wm * 64 + mi * 16 + (lane >> 2);
#pragma unroll
        for (int ni = 0; ni < 4; ni++) {
            int lc = f0 + wn * 16 + ni * 4 + (lane & 3);
            float* d = acc[mi][ni];
            if (r < me)
                g_hb_h[(size_t)(roff + r) * FDIM + lc] = __float2half_rn(silu_mul_fast(d[0], d[1]));
            if (r + 8 < me)
                g_hb_h[(size_t)(roff + r + 8) * FDIM + lc] = __float2half_rn(silu_mul_fast(d[2], d[3]));
        }
    }
}

// =====================================================================
// Expert GEMM2 (half = tile table index)
// =====================================================================
__global__ void __launch_bounds__(256, 2) eg2_kernel(const float* __restrict__ w2,
                                                     float* __restrict__ out,
                                                     int half) {
    extern __shared__ char sm[];
    const int tid = threadIdx.x, lane = tid & 31, wid = tid >> 5;
    const int wm = wid & 1, wn = wid >> 1;
    const int t = blockIdx.x;
    if (t >= g_nt2[half] * 8) return;
    const int tile = g_tiles2[half][t >> 3];
    const int e  = tile >> 8;
    const int m0 = (tile & 255) * 128;
    const int n0 = (t & 7) * 128;
    const int me = g_ecount[e];
    const int roff = g_offsets[e];
    const uint32_t smb = smem_u32(sm);

    int*   toks = (int*)sm;
    float* wro  = (float*)(sm + 512);
    if (tid < 128) {
        int m = m0 + tid;
        bool v = m < me;
        toks[tid] = v ? g_row_token[roff + m] : 0;
        wro[tid]  = v ? g_row_weight[roff + m] : 0.f;
    }
    __syncthreads();

    const int lr = tid >> 1, kseg = (tid & 1) * 16;
    const uint32_t soff = (uint32_t)(lr * STRIDE + kseg * 2);
    int mm = m0 + lr;
    size_t arow = (size_t)(roff + ((mm < me) ? mm : (me - 1)));
    const __half* axh = g_hb_h + arow * FDIM + kseg;
    const float* bp = w2 + ((size_t)e * HDIM + n0 + lr) * FDIM + kseg;

    float acc[4][4][4];
#pragma unroll
    for (int i = 0; i < 4; i++)
#pragma unroll
        for (int j = 0; j < 4; j++)
#pragma unroll
            for (int k = 0; k < 4; k++) acc[i][j][k] = 0.f;

    const int NCH = FDIM / 32;
    float rb[16], rbn[16];
    ldg16f(rb, bp);
    sts_h16(sm + toff(0, 1) + soff, rb);
    ldg16f(rb, bp + 32);
    sts_h16(sm + toff(1, 1) + soff, rb);
    ldg16f(rbn, bp + 64);
    cp32B(smb + toff(0, 0) + soff, axh);
    CP_COMMIT();
    cp32B(smb + toff(1, 0) + soff, axh + 32);
    CP_COMMIT();

    for (int ch = 0; ch < NCH; ch++) {
        if (ch + 1 < NCH) CP_WAIT1(); else CP_WAIT0();
        __syncthreads();
        if (ch + 2 < NCH) {
            int st = (ch + 2) % 3;
            sts_h16(sm + toff(st, 1) + soff, rbn);
            cp32B(smb + toff(st, 0) + soff, axh + (ch + 2) * 32);
            CP_COMMIT();
            if (ch + 3 < NCH) ldg16f(rbn, bp + (ch + 3) * 32);
        }
        mma_tile1(acc, smb, ch % 3, wm, wn, lane);
    }

#pragma unroll
    for (int mi = 0; mi < 4; mi++) {
        int lrow = wm * 64 + mi * 16 + (lane >> 2);
        int r = m0 + lrow;
        int t0 = toks[lrow], t1 = toks[lrow + 8];
        float w0 = wro[lrow], w1v = wro[lrow + 8];
#pragma unroll
        for (int ni = 0; ni < 4; ni++) {
            int col = n0 + wn * 32 + ni * 8 + 2 * (lane & 3);
            float* d = acc[mi][ni];
            if (r < me) {
                atomicAdd(out + (size_t)t0 * HDIM + col,     d[0] * w0);
                atomicAdd(out + (size_t)t0 * HDIM + col + 1, d[1] * w0);
            }
            if (r + 8 < me) {
                atomicAdd(out + (size_t)t1 * HDIM + col,     d[2] * w1v);
                atomicAdd(out + (size_t)t1 * HDIM + col + 1, d[3] * w1v);
            }
        }
    }
}

// =====================================================================
// Shared GEMM1
// =====================================================================
__global__ void __launch_bounds__(256, 2) sg1_kernel() {
    extern __shared__ char sm[];
    const int tid = threadIdx.x, lane = tid & 31, wid = tid >> 5;
    const int wm = wid & 1, wn = wid >> 1;
    const int m0 = blockIdx.y * 128;
    const int f0 = blockIdx.x * 64;
    const uint32_t smb = smem_u32(sm);

    const int lr = tid >> 1, kseg = (tid & 1) * 16;
    const uint32_t soff = (uint32_t)(lr * STRIDE + kseg * 2);
    const __half* axh = g_x_h + (size_t)(m0 + lr) * HDIM + kseg;
    const __half* bxh = ((lr & 1) ? g_su_h : g_sg_h) + (size_t)(f0 + (lr >> 1)) * HDIM + kseg;

    float acc[4][4][4];
#pragma unroll
    for (int i = 0; i < 4; i++)
#pragma unroll
        for (int j = 0; j < 4; j++)
#pragma unroll
            for (int k = 0; k < 4; k++) acc[i][j][k] = 0.f;

    const int NCH = HDIM / 32;
    cp32B(smb + toff(0, 0) + soff, axh);
    cp32B(smb + toff(0, 1) + soff, bxh);
    CP_COMMIT();
    cp32B(smb + toff(1, 0) + soff, axh + 32);
    cp32B(smb + toff(1, 1) + soff, bxh + 32);
    CP_COMMIT();

    for (int ch = 0; ch < NCH; ch++) {
        if (ch + 1 < NCH) CP_WAIT1(); else CP_WAIT0();
        __syncthreads();
        if (ch + 2 < NCH) {
            int st = (ch + 2) % 3;
            int k0 = (ch + 2) * 32;
            cp32B(smb + toff(st, 0) + soff, axh + k0);
            cp32B(smb + toff(st, 1) + soff, bxh + k0);
            CP_COMMIT();
        }
        mma_tile1(acc, smb, ch % 3, wm, wn, lane);
    }

#pragma unroll
    for (int mi = 0; mi < 4; mi++) {
        int r = m0 + wm * 64 + mi * 16 + (lane >> 2);
#pragma unroll
        for (int ni = 0; ni < 4; ni++) {
            int lc = f0 + wn * 16 + ni * 4 + (lane & 3);
            float* d = acc[mi][ni];
            g_hs_h[(size_t)r * F2DIM + lc]       = __float2half_rn(silu_mul_fast(d[0], d[1]));
            g_hs_h[(size_t)(r + 8) * F2DIM + lc] = __float2half_rn(silu_mul_fast(d[2], d[3]));
        }
    }
}

// =====================================================================
// Shared GEMM2
// =====================================================================
__global__ void __launch_bounds__(256, 2) sg2_kernel(float* __restrict__ out) {
    extern __shared__ char sm[];
    const int tid = threadIdx.x, lane = tid & 31, wid = tid >> 5;
    const int wm = wid & 1, wn = wid >> 1;
    const int m0 = blockIdx.y * 128;
    const int n0 = blockIdx.x * 128;
    const uint32_t smb = smem_u32(sm);

    const int lr = tid >> 1, kseg = (tid & 1) * 16;
    const uint32_t soff = (uint32_t)(lr * STRIDE + kseg * 2);
    const __half* axh = g_hs_h + (size_t)(m0 + lr) * F2DIM + kseg;
    const __half* bxh = g_sd_h + (size_t)(n0 + lr) * F2DIM + kseg;

    float acc[4][4][4];
#pragma unroll
    for (int i = 0; i < 4; i++)
#pragma unroll
        for (int j = 0; j < 4; j++)
#pragma unroll
            for (int k = 0; k < 4; k++) acc[i][j][k] = 0.f;

    const int NCH = F2DIM / 32;
    cp32B(smb + toff(0, 0) + soff, axh);
    cp32B(smb + toff(0, 1) + soff, bxh);
    CP_COMMIT();
    cp32B(smb + toff(1, 0) + soff, axh + 32);
    cp32B(smb + toff(1, 1) + soff, bxh + 32);
    CP_COMMIT();

    for (int ch = 0; ch < NCH; ch++) {
        if (ch + 1 < NCH) CP_WAIT1(); else CP_WAIT0();
        __syncthreads();
        if (ch + 2 < NCH) {
            int st = (ch + 2) % 3;
            int k0 = (ch + 2) * 32;
            cp32B(smb + toff(st, 0) + soff, axh + k0);
            cp32B(smb + toff(st, 1) + soff, bxh + k0);
            CP_COMMIT();
        }
        mma_tile1(acc, smb, ch % 3, wm, wn, lane);
    }

#pragma unroll
    for (int mi = 0; mi < 4; mi++) {
        int r = m0 + wm * 64 + mi * 16 + (lane >> 2);
#pragma unroll
        for (int ni = 0; ni < 4; ni++) {
            int col = n0 + wn * 32 + ni * 8 + 2 * (lane & 3);
            float* d = acc[mi][ni];
            *(float2*)(out + (size_t)r * HDIM + col)       = make_float2(d[0], d[1]);
            *(float2*)(out + (size_t)(r + 8) * HDIM + col) = make_float2(d[2], d[3]);
        }
    }
}

// ---------------- launch ----------------
extern "C" void kernel_launch(void* const* d_in, const int* in_sizes, int n_in,
                              void* d_out, int out_size) {
    const float* x   = (const float*)d_in[0];
    const float* gw  = (const float*)d_in[1];
    const float* eb  = (const float*)d_in[2];
    const float* w1  = (const float*)d_in[3];
    const float* w2  = (const float*)d_in[4];
    const float* w3  = (const float*)d_in[5];
    const float* sg  = (const float*)d_in[6];
    const float* su  = (const float*)d_in[7];
    const float* sd  = (const float*)d_in[8];
    float* out = (float*)d_out;

    static bool init_done = false;
    static cudaStream_t s2;
    static cudaEvent_t evA, evAsn, evB, evC;
    if (!init_done) {
        cudaFuncSetAttribute(logits_kernel, cudaFuncAttributeMaxDynamicSharedMemorySize, SMEM_LOG);
        cudaFuncSetAttribute(eg1_kernel, cudaFuncAttributeMaxDynamicSharedMemorySize, SMEM_GEMM);
        cudaFuncSetAttribute(sg1_kernel, cudaFuncAttributeMaxDynamicSharedMemorySize, SMEM_GEMM);
        cudaFuncSetAttribute(eg2_kernel, cudaFuncAttributeMaxDynamicSharedMemorySize, SMEM_GEMM);
        cudaFuncSetAttribute(sg2_kernel, cudaFuncAttributeMaxDynamicSharedMemorySize, SMEM_GEMM);
        cudaStreamCreateWithFlags(&s2, cudaStreamNonBlocking);
        cudaEventCreateWithFlags(&evA,   cudaEventDisableTiming);
        cudaEventCreateWithFlags(&evAsn, cudaEventDisableTiming);
        cudaEventCreateWithFlags(&evB,   cudaEventDisableTiming);
        cudaEventCreateWithFlags(&evC,   cudaEventDisableTiming);
        init_done = true;
    }

    // presplit: shared weights on s2, x+gw on main
    presplitB_kernel<<<dim3(NS / 256, 3), 256, 0, s2>>>(sg, su, sd);
    presplitA_kernel<<<(NX + NG + 255) / 256, 256>>>(x, gw);
    cudaEventRecord(evA, 0);
    cudaStreamWaitEvent(s2, evA, 0);   // sg1 needs g_x_h

    // branch B on s2: shared expert, then expert chain half 1
    sg1_kernel<<<dim3(F2DIM / 64, TOK / 128), 256, SMEM_GEMM, s2>>>();
    sg2_kernel<<<dim3(HDIM / 128, TOK / 128), 256, SMEM_GEMM, s2>>>(out);
    cudaEventRecord(evB, s2);

    // branch A on main: routing -> dispatch
    logits_kernel<<<dim3(TOK / 128, KSPLIT), 256, SMEM_LOG>>>();
    topk_kernel<<<TOK / 8, 256>>>(eb);
    assign_kernel<<<SKTOT / 256, 256>>>();
    cudaEventRecord(evAsn, 0);

    // chain half 0 (main): eg1 -> (wait sg2) -> eg2
    eg1_kernel<<<HTILES * 8, 256, SMEM_GEMM>>>(w1, w3, 0);

    // chain half 1 (s2): needs assign; sg2 already ordered on s2
    cudaStreamWaitEvent(s2, evAsn, 0);
    eg1_kernel<<<HTILES * 8, 256, SMEM_GEMM, s2>>>(w1, w3, 1);
    eg2_kernel<<<HTILES * 8, 256, SMEM_GEMM, s2>>>(w2, out, 1);
    cudaEventRecord(evC, s2);

    cudaStreamWaitEvent(0, evB, 0);    // eg2(0) needs sg2's out
    eg2_kernel<<<HTILES * 8, 256, SMEM_GEMM>>>(w2, out, 0);
    cudaStreamWaitEvent(0, evC, 0);    // join s2 into main before capture end
}